// round 14
// baseline (speedup 1.0000x reference)
#include <cuda_runtime.h>
#include <cuda_bf16.h>

#define B_   8
#define C_   192
#define CQ   32
#define N_   16384
#define NPIX (B_ * N_)
#define EPSF 1e-6f

typedef unsigned long long u64;

// ---------------- scratch ---------------------------------------------------
__device__ float g_Qn[(size_t)NPIX * CQ];   // [px][32] normalized Q
__device__ float g_Kn[(size_t)NPIX * CQ];   // [px][32] normalized K
__device__ float g_G[B_ * 33 * C_];         // rows 0..31: G[m][k]; row 32: xsum[k]
__device__ float g_KS[B_ * CQ];             // sum_n Kn
__device__ float g_M[B_ * 33 * C_];         // rows 0..31: matrix[m][c]; row 32: value_sum[c]

// ---------------- helpers -----------------------------------------------------
__device__ __forceinline__ void red2(float* p, float lo, float hi) {
    asm volatile("red.global.add.v2.f32 [%0], {%1, %2};"
                 :: "l"(p), "f"(lo), "f"(hi) : "memory");
}
__device__ __forceinline__ void mma_bf16(float* c, const unsigned* a, unsigned b0, unsigned b1) {
    asm volatile(
        "mma.sync.aligned.m16n8k16.row.col.f32.bf16.bf16.f32 "
        "{%0,%1,%2,%3}, {%4,%5,%6,%7}, {%8,%9}, {%0,%1,%2,%3};"
        : "+f"(c[0]), "+f"(c[1]), "+f"(c[2]), "+f"(c[3])
        : "r"(a[0]), "r"(a[1]), "r"(a[2]), "r"(a[3]), "r"(b0), "r"(b1));
}
__device__ __forceinline__ unsigned split_pair(float v0, float v1, unsigned& lo_out) {
    __nv_bfloat162 hv = __floats2bfloat162_rn(v0, v1);
    float h0 = __bfloat162float(hv.x), h1 = __bfloat162float(hv.y);
    __nv_bfloat162 lv = __floats2bfloat162_rn(v0 - h0, v1 - h1);
    lo_out = *(unsigned*)&lv;
    return *(unsigned*)&hv;
}

// ---------------- K1: Q/K projection via mma.sync split-bf16 ------------------
#define QKA_OFF 1024
#define QKB_OFF (1024 + 131072)
#define QK_SMEM (QKB_OFF + 65536)    /* 197632 B */

__device__ __forceinline__ void cvt_split8(const float* v, uint4& hi4, uint4& lo4) {
    unsigned hp[4], lp[4];
#pragma unroll
    for (int e = 0; e < 4; e++)
        hp[e] = split_pair(v[2 * e], v[2 * e + 1], lp[e]);
    hi4 = make_uint4(hp[0], hp[1], hp[2], hp[3]);
    lo4 = make_uint4(lp[0], lp[1], lp[2], lp[3]);
}

__global__ void __launch_bounds__(256, 1) k_qk(
    const float* __restrict__ x1,
    const float* __restrict__ Wq, const float* __restrict__ bq,
    const float* __restrict__ Wk, const float* __restrict__ bk)
{
    extern __shared__ __align__(16) char smem[];
    float* sbias = (float*)smem;
    int tid = threadIdx.x;
    int b  = blockIdx.x >> 7;
    int n0 = (blockIdx.x & 127) << 7;

    // zero accumulators for k_gmat
    {
        int z = blockIdx.x * 256 + tid;
        if (z < B_ * 33 * C_) g_G[z] = 0.0f;
        int zk = z - B_ * 33 * C_;
        if (zk >= 0 && zk < B_ * CQ) g_KS[zk] = 0.0f;
    }

    if (tid < 32)       sbias[tid] = bq[tid];
    else if (tid < 64)  sbias[tid] = bk[tid - 32];

    // stage A: x1 tile 128px x 192k -> hi at bytes [0,384), lo at [384,768)
    {
        int px = tid & 127, half = tid >> 7;
        const float* xb = x1 + (size_t)b * C_ * N_ + n0 + px;
        char* arow = smem + QKA_OFF + px * 1024;
        unsigned sw = (px & 7) << 4;
        for (int c = half * 12; c < half * 12 + 12; c++) {
            float v[8];
#pragma unroll
            for (int j = 0; j < 8; j++) v[j] = xb[(size_t)(8 * c + j) * N_];
            uint4 hi4, lo4;
            cvt_split8(v, hi4, lo4);
            *(uint4*)(arow + ((16u * c) ^ sw))        = hi4;
            *(uint4*)(arow + ((384u + 16u * c) ^ sw)) = lo4;
        }
    }
    // stage B: W rows (0-31 Wq, 32-63 Wk) -> lo at [0,384), hi at [384,768)
    for (int i = tid; i < 1536; i += 256) {
        int n = i & 63, c = i >> 6;
        const float* wr = (n < 32) ? (Wq + (size_t)n * C_) : (Wk + (size_t)(n - 32) * C_);
        char* brow = smem + QKB_OFF + n * 1024;
        unsigned sw = (n & 7) << 4;
        float v[8];
#pragma unroll
        for (int j = 0; j < 8; j++) v[j] = wr[8 * c + j];
        uint4 hi4, lo4;
        cvt_split8(v, hi4, lo4);
        *(uint4*)(brow + ((16u * c) ^ sw))        = lo4;
        *(uint4*)(brow + ((384u + 16u * c) ^ sw)) = hi4;
    }
    __syncthreads();

    int lane = tid & 31, g = lane >> 2, t = lane & 3;
    int w = tid >> 5, mpair = w >> 1, nhalf = w & 1;
    const char* Abase = smem + QKA_OFF + (mpair * 32) * 1024;
    const char* Bbase = smem + QKB_OFF + (nhalf * 32) * 1024;
    unsigned swg = (unsigned)g << 4;

    float cfr[2][4][4];
#pragma unroll
    for (int mt = 0; mt < 2; mt++)
#pragma unroll
        for (int nt = 0; nt < 4; nt++)
#pragma unroll
            for (int e = 0; e < 4; e++) cfr[mt][nt][e] = 0.f;

    for (int s = 0; s < 36; s++) {
        unsigned ka = (s < 24) ? 32u * s : 32u * (s - 24);
        unsigned kb = (s < 24) ? 32u * s : 384u + 32u * (s - 24);
        unsigned ka0 = (ka + 4 * t) ^ swg;
        unsigned ka1 = (ka + 4 * t + 16) ^ swg;
        unsigned kb0 = (kb + 4 * t) ^ swg;
        unsigned kb1 = (kb + 4 * t + 16) ^ swg;

        unsigned a[2][4];
#pragma unroll
        for (int mt = 0; mt < 2; mt++) {
            const char* r1 = Abase + (16 * mt + g) * 1024;
            const char* r2 = r1 + 8 * 1024;
            a[mt][0] = *(const unsigned*)(r1 + ka0);
            a[mt][1] = *(const unsigned*)(r2 + ka0);
            a[mt][2] = *(const unsigned*)(r1 + ka1);
            a[mt][3] = *(const unsigned*)(r2 + ka1);
        }
#pragma unroll
        for (int nt = 0; nt < 4; nt++) {
            const char* nr = Bbase + (nt * 8 + g) * 1024;
            unsigned b0 = *(const unsigned*)(nr + kb0);
            unsigned b1 = *(const unsigned*)(nr + kb1);
#pragma unroll
            for (int mt = 0; mt < 2; mt++)
                mma_bf16(cfr[mt][nt], a[mt], b0, b1);
        }
    }

    // epilogue: bias, L2 norm (reduce over t-group), store
#pragma unroll
    for (int mt = 0; mt < 2; mt++) {
        float s0 = 0.f, s1 = 0.f;
#pragma unroll
        for (int nt = 0; nt < 4; nt++) {
            float b0 = sbias[nhalf * 32 + nt * 8 + 2 * t];
            float b1 = sbias[nhalf * 32 + nt * 8 + 2 * t + 1];
            cfr[mt][nt][0] += b0; cfr[mt][nt][1] += b1;
            cfr[mt][nt][2] += b0; cfr[mt][nt][3] += b1;
            s0 += cfr[mt][nt][0] * cfr[mt][nt][0] + cfr[mt][nt][1] * cfr[mt][nt][1];
            s1 += cfr[mt][nt][2] * cfr[mt][nt][2] + cfr[mt][nt][3] * cfr[mt][nt][3];
        }
        s0 += __shfl_xor_sync(0xffffffffu, s0, 1);
        s0 += __shfl_xor_sync(0xffffffffu, s0, 2);
        s1 += __shfl_xor_sync(0xffffffffu, s1, 1);
        s1 += __shfl_xor_sync(0xffffffffu, s1, 2);
        float r0 = rsqrtf(s0), r1v = rsqrtf(s1);

        int px0 = n0 + mpair * 32 + 16 * mt + g;
        float* dst = nhalf ? g_Kn : g_Qn;
        float* d0 = dst + ((size_t)b * N_ + px0) * CQ;
        float* d1 = d0 + 8 * CQ;
#pragma unroll
        for (int nt = 0; nt < 4; nt++) {
            int col = nt * 8 + 2 * t;
            *(float2*)(d0 + col) = make_float2(cfr[mt][nt][0] * r0, cfr[mt][nt][1] * r0);
            *(float2*)(d1 + col) = make_float2(cfr[mt][nt][2] * r1v, cfr[mt][nt][3] * r1v);
        }
    }
}

// ---------------- K2: G = Kn^T @ x^T via mma.sync split-bf16 ------------------
#define GM_BH  0
#define GM_BL  27648
#define GM_AH  55296
#define GM_AL  59904
#define GM_SMEM 64512

__global__ void __launch_bounds__(256, 2) k_gmat(const float* __restrict__ x)
{
    extern __shared__ __align__(16) char smg[];
    char* Bh = smg + GM_BH;
    char* Bl = smg + GM_BL;
    char* Ah = smg + GM_AH;
    char* Al = smg + GM_AL;
    __shared__ float sKS[32];

    int tid = threadIdx.x, lane = tid & 31, w = tid >> 5;
    int g = lane >> 2, t = lane & 3;
    int mt = w & 1, ng = w >> 1;
    int b  = blockIdx.x >> 5;
    int n0 = (blockIdx.x & 31) << 9;

    const float* xb  = x + (size_t)b * C_ * N_ + n0;
    const float* knb = g_Kn + ((size_t)b * N_ + n0) * CQ;

    if (tid < 32) sKS[tid] = 0.f;

    float accf[6][4];
#pragma unroll
    for (int j = 0; j < 6; j++)
#pragma unroll
        for (int e = 0; e < 4; e++) accf[j][e] = 0.f;
    float xs[24];
#pragma unroll
    for (int j = 0; j < 24; j++) xs[j] = 0.f;
    float ksacc = 0.f;

    for (int s = 0; s < 8; s++) {
        int ns = s * 64;
        __syncthreads();

        // stage A: px 8w..8w+7, m = lane; k-pair-packed u32
        {
            float v[8];
#pragma unroll
            for (int j = 0; j < 8; j++) {
                v[j] = knb[(size_t)(ns + 8 * w + j) * CQ + lane];
                ksacc += v[j];
            }
#pragma unroll
            for (int jj = 0; jj < 4; jj++) {
                unsigned lo, hi = split_pair(v[2 * jj], v[2 * jj + 1], lo);
                *(unsigned*)(Ah + lane * 144 + (4 * w + jj) * 4) = hi;
                *(unsigned*)(Al + lane * 144 + (4 * w + jj) * 4) = lo;
            }
        }
        // stage B: rows w*24 .. w*24+23, 64 k (float2 per lane)
#pragma unroll
        for (int r0 = 0; r0 < 24; r0++) {
            int r = w * 24 + r0;
            float2 xv = *(const float2*)(xb + (size_t)r * N_ + ns + 2 * lane);
            xs[r0] += xv.x + xv.y;
            unsigned lo, hi = split_pair(xv.x, xv.y, lo);
            *(unsigned*)(Bh + r * 144 + 4 * lane) = hi;
            *(unsigned*)(Bl + r * 144 + 4 * lane) = lo;
        }
        __syncthreads();

        // MMA: 4 ksteps of 16
#pragma unroll
        for (int ks = 0; ks < 4; ks++) {
            unsigned ah[4], al[4];
            const char* ar0 = Ah + (16 * mt + g) * 144 + 32 * ks + 4 * t;
            const char* ar1 = ar0 + 8 * 144;
            ah[0] = *(const unsigned*)(ar0);
            ah[1] = *(const unsigned*)(ar1);
            ah[2] = *(const unsigned*)(ar0 + 16);
            ah[3] = *(const unsigned*)(ar1 + 16);
            const char* br0 = Al + (16 * mt + g) * 144 + 32 * ks + 4 * t;
            const char* br1 = br0 + 8 * 144;
            al[0] = *(const unsigned*)(br0);
            al[1] = *(const unsigned*)(br1);
            al[2] = *(const unsigned*)(br0 + 16);
            al[3] = *(const unsigned*)(br1 + 16);
#pragma unroll
            for (int j = 0; j < 6; j++) {
                int r = ng * 48 + j * 8 + g;
                const char* bhp = Bh + r * 144 + 32 * ks + 4 * t;
                const char* blp = Bl + r * 144 + 32 * ks + 4 * t;
                unsigned bh0 = *(const unsigned*)(bhp);
                unsigned bh1 = *(const unsigned*)(bhp + 16);
                unsigned bl0 = *(const unsigned*)(blp);
                unsigned bl1 = *(const unsigned*)(blp + 16);
                mma_bf16(accf[j], ah, bh0, bh1);   // hi*hi
                mma_bf16(accf[j], ah, bl0, bl1);   // hi*lo
                mma_bf16(accf[j], al, bh0, bh1);   // lo*hi
            }
        }
    }

    float* gb = g_G + b * 33 * C_;
#pragma unroll
    for (int j = 0; j < 6; j++) {
        int col = ng * 48 + j * 8 + 2 * t;
        red2(gb + (16 * mt + g) * C_ + col,     accf[j][0], accf[j][1]);
        red2(gb + (16 * mt + g + 8) * C_ + col, accf[j][2], accf[j][3]);
    }
#pragma unroll
    for (int j = 0; j < 24; j++) {
        float vv = xs[j];
        vv += __shfl_xor_sync(0xffffffffu, vv, 16);
        vv += __shfl_xor_sync(0xffffffffu, vv, 8);
        vv += __shfl_xor_sync(0xffffffffu, vv, 4);
        vv += __shfl_xor_sync(0xffffffffu, vv, 2);
        vv += __shfl_xor_sync(0xffffffffu, vv, 1);
        if (lane == 0) atomicAdd(gb + 32 * C_ + w * 24 + j, vv);
    }
    atomicAdd(&sKS[lane], ksacc);
    __syncthreads();
    if (tid < 32) atomicAdd(&g_KS[b * CQ + tid], sKS[tid]);
}

// ---------------- K3: M' = Ghat @ Wv^T + outer(coef, bv) ---------------------
__global__ void __launch_bounds__(128) k_small(
    const float* __restrict__ Wv, const float* __restrict__ bv)
{
    extern __shared__ float sms[];
    float* sG  = sms;                 // [33][192]
    float* sWv = sms + 33 * C_;       // [32][193]
    int tid = threadIdx.x;
    int b  = blockIdx.x / 6;
    int ct = blockIdx.x % 6;
    int cl = tid & 31, mg = tid >> 5;
    int c  = ct * 32 + cl;

    for (int i = tid; i < 33 * C_; i += 128) sG[i] = g_G[b * 33 * C_ + i];
    for (int i = tid; i < 32 * C_; i += 128) {
        int cc = i / C_, k = i % C_;
        sWv[cc * 193 + k] = Wv[(size_t)(ct * 32 + cc) * C_ + k];
    }
    __syncthreads();

    float bvc = bv[c];
    float a[9];
#pragma unroll
    for (int rr = 0; rr < 8; rr++) a[rr] = g_KS[b * CQ + mg * 8 + rr] * bvc;
    a[8] = (float)N_ * bvc;

    const float* wp = sWv + cl * 193;
    for (int k = 0; k < C_; k += 2) {
        float w0 = wp[k], w1 = wp[k + 1];
#pragma unroll
        for (int rr = 0; rr < 8; rr++) {
            int r = mg * 8 + rr;
            a[rr] = fmaf(w0, sG[r * C_ + k], a[rr]);
            a[rr] = fmaf(w1, sG[r * C_ + k + 1], a[rr]);
        }
        if (mg == 3) {
            a[8] = fmaf(w0, sG[32 * C_ + k], a[8]);
            a[8] = fmaf(w1, sG[32 * C_ + k + 1], a[8]);
        }
    }
#pragma unroll
    for (int rr = 0; rr < 8; rr++)
        g_M[(b * 33 + mg * 8 + rr) * C_ + c] = a[rr];
    if (mg == 3)
        g_M[(b * 33 + 32) * C_ + c] = a[8];
}

// ---------------- K4: out = A @ M' via mma.sync split-bf16 --------------------
// 2048 blocks = 8b x 128 n-slices(128px) x 2 c-halves(96c); 256 thr, 3/SM.
// Coalesced epilogue: fragments -> smem tile (144-float rows, conflict-free)
// -> float4 global stores (512B/instr), two 48-c halves.
#define KO_A_OFF  0
#define KO_B_OFF  26624                /* 128*208 */
#define KO_SMEM   (26624 + 19968)      /* + 96*208 = 46592 */

__global__ void __launch_bounds__(256, 3) k_out(
    const float* __restrict__ gamma, float* __restrict__ out)
{
    extern __shared__ __align__(16) char smo[];
    char* sA = smo + KO_A_OFF;
    char* sB = smo + KO_B_OFF;
    float* sOut = (float*)smo;         // reused after MMA: [48][144] floats
    __shared__ float sKS[CQ];
    int tid = threadIdx.x;
    int b  = blockIdx.x >> 8;
    int ns = (blockIdx.x >> 1) & 127;
    int ch = blockIdx.x & 1;
    int n0 = ns << 7;

    if (tid < CQ) sKS[tid] = g_KS[b * CQ + tid] + EPSF;

    // ---- stage B: 96 c-rows x 24 kk-pairs, hi+lo (transpose of g_M half)
    {
        const float* mb = g_M + b * 33 * C_ + ch * 96;
#pragma unroll
        for (int i = 0; i < 9; i++) {
            int j = tid + 256 * i;          // 2304 jobs
            int kk = j / 96, cc = j % 96;
            float m0 = (2 * kk < 33)     ? mb[(2 * kk) * C_ + cc]     : 0.f;
            float m1 = (2 * kk + 1 < 33) ? mb[(2 * kk + 1) * C_ + cc] : 0.f;
            unsigned lo, hi = split_pair(m0, m1, lo);
            *(unsigned*)(sB + cc * 208 + 4 * kk)      = hi;
            *(unsigned*)(sB + cc * 208 + 96 + 4 * kk) = lo;
        }
    }
    __syncthreads();          // sKS visible for A staging

    // ---- stage A: row px = tid (tid<128): a[k] = g*Qn[k], a[32] = g
    if (tid < 128) {
        const float4* qsrc = (const float4*)(g_Qn + ((size_t)b * N_ + n0 + tid) * CQ);
        float qv[32];
#pragma unroll
        for (int jj = 0; jj < 8; jj++) {
            float4 v = qsrc[jj];
            qv[4 * jj] = v.x; qv[4 * jj + 1] = v.y;
            qv[4 * jj + 2] = v.z; qv[4 * jj + 3] = v.w;
        }
        float dot = 0.f;
#pragma unroll
        for (int m = 0; m < CQ; m++) dot += qv[m] * sKS[m];
        float gsc = gamma[0] / ((float)N_ + dot);

        char* arow = sA + tid * 208;
#pragma unroll
        for (int kk = 0; kk < 16; kk++) {
            unsigned lo, hi = split_pair(qv[2 * kk] * gsc, qv[2 * kk + 1] * gsc, lo);
            *(unsigned*)(arow + 4 * kk)      = hi;
            *(unsigned*)(arow + 96 + 4 * kk) = lo;
        }
        {   // kk = 16: (g, 0)
            unsigned lo, hi = split_pair(gsc, 0.f, lo);
            *(unsigned*)(arow + 64)      = hi;
            *(unsigned*)(arow + 96 + 64) = lo;
        }
#pragma unroll
        for (int kk = 17; kk < 24; kk++) {
            *(unsigned*)(arow + 4 * kk)      = 0u;
            *(unsigned*)(arow + 96 + 4 * kk) = 0u;
        }
    }
    __syncthreads();

    // ---- MMA: warp w = m-tile (rows w*16 + g, +8), nt = 0..11, K=48
    int lane = tid & 31, g = lane >> 2, t = lane & 3;
    int w = tid >> 5;

    float cfr[12][4];
#pragma unroll
    for (int nt = 0; nt < 12; nt++)
#pragma unroll
        for (int e = 0; e < 4; e++) cfr[nt][e] = 0.f;

    const char* ar0 = sA + (w * 16 + g) * 208 + 4 * t;
    const char* ar1 = ar0 + 8 * 208;

#pragma unroll
    for (int ks = 0; ks < 3; ks++) {
        unsigned ah[4], al[4];
        ah[0] = *(const unsigned*)(ar0 + 32 * ks);
        ah[1] = *(const unsigned*)(ar1 + 32 * ks);
        ah[2] = *(const unsigned*)(ar0 + 32 * ks + 16);
        ah[3] = *(const unsigned*)(ar1 + 32 * ks + 16);
        al[0] = *(const unsigned*)(ar0 + 96 + 32 * ks);
        al[1] = *(const unsigned*)(ar1 + 96 + 32 * ks);
        al[2] = *(const unsigned*)(ar0 + 96 + 32 * ks + 16);
        al[3] = *(const unsigned*)(ar1 + 96 + 32 * ks + 16);
#pragma unroll
        for (int nt = 0; nt < 12; nt++) {
            const char* brow = sB + (nt * 8 + g) * 208 + 32 * ks + 4 * t;
            unsigned bh0 = *(const unsigned*)(brow);
            unsigned bh1 = *(const unsigned*)(brow + 16);
            mma_bf16(cfr[nt], ah, bh0, bh1);       // hi*hi
            mma_bf16(cfr[nt], al, bh0, bh1);       // lo*hi
            unsigned bl0 = *(const unsigned*)(brow + 96);
            unsigned bl1 = *(const unsigned*)(brow + 96 + 16);
            mma_bf16(cfr[nt], ah, bl0, bl1);       // hi*lo
        }
    }

    // ---- coalesced epilogue: two 48-c halves through smem
    int pxl = w * 16 + g;                  // local px of rows c0/c1 (c2/c3 at +8)
    float* obase = out + ((size_t)b * C_ + ch * 96) * N_ + n0;
#pragma unroll
    for (int h = 0; h < 2; h++) {
        __syncthreads();                   // sA/sB reads (h=0) or prior copy (h=1) done
#pragma unroll
        for (int j = 0; j < 6; j++) {
            int nt = h * 6 + j;
            int cl = j * 8 + 2 * t;        // c-row within half
            sOut[cl * 144 + pxl]           = cfr[nt][0];
            sOut[(cl + 1) * 144 + pxl]     = cfr[nt][1];
            sOut[cl * 144 + pxl + 8]       = cfr[nt][2];
            sOut[(cl + 1) * 144 + pxl + 8] = cfr[nt][3];
        }
        __syncthreads();
#pragma unroll
        for (int i = 0; i < 6; i++) {
            int j = tid + 256 * i;         // 1536 float4 jobs
            int row = j >> 5, q = j & 31;
            float4 v = ((const float4*)(sOut + row * 144))[q];
            *(float4*)(obase + (size_t)(h * 48 + row) * N_ + 4 * q) = v;
        }
    }
}

// ---------------- launch ------------------------------------------------------
extern "C" void kernel_launch(void* const* d_in, const int* in_sizes, int n_in,
                              void* d_out, int out_size)
{
    const float* x     = (const float*)d_in[0];
    const float* x1    = (const float*)d_in[1];
    const float* Wq    = (const float*)d_in[2];
    const float* bq    = (const float*)d_in[3];
    const float* Wk    = (const float*)d_in[4];
    const float* bk    = (const float*)d_in[5];
    const float* Wv    = (const float*)d_in[6];
    const float* bv    = (const float*)d_in[7];
    const float* gamma = (const float*)d_in[8];
    float* out = (float*)d_out;

    static int inited = 0;
    if (!inited) {
        cudaFuncSetAttribute(k_qk,    cudaFuncAttributeMaxDynamicSharedMemorySize, QK_SMEM);
        cudaFuncSetAttribute(k_gmat,  cudaFuncAttributeMaxDynamicSharedMemorySize, GM_SMEM);
        cudaFuncSetAttribute(k_small, cudaFuncAttributeMaxDynamicSharedMemorySize, 50080);
        cudaFuncSetAttribute(k_out,   cudaFuncAttributeMaxDynamicSharedMemorySize, KO_SMEM);
        inited = 1;
    }

    k_qk   <<<1024, 256, QK_SMEM>>>(x1, Wq, bq, Wk, bk);
    k_gmat <<<256, 256, GM_SMEM>>>(x);
    k_small<<<48, 128, 50080>>>(Wv, bv);
    k_out  <<<2048, 256, KO_SMEM>>>(gamma, out);
}

// round 15
// speedup vs baseline: 1.0971x; 1.0971x over previous
#include <cuda_runtime.h>
#include <cuda_bf16.h>

#define B_   8
#define C_   192
#define CQ   32
#define N_   16384
#define NPIX (B_ * N_)
#define EPSF 1e-6f

typedef unsigned long long u64;

// ---------------- scratch ---------------------------------------------------
__device__ float g_Qn[(size_t)NPIX * CQ];   // [px][32] normalized Q
__device__ float g_Kn[(size_t)NPIX * CQ];   // [px][32] normalized K
__device__ float g_G[B_ * 33 * C_];         // rows 0..31: G[m][k]; row 32: xsum[k]
__device__ float g_KS[B_ * CQ];             // sum_n Kn
__device__ float g_M[B_ * 33 * C_];         // rows 0..31: matrix[m][c]; row 32: value_sum[c]

// ---------------- helpers -----------------------------------------------------
__device__ __forceinline__ void red2(float* p, float lo, float hi) {
    asm volatile("red.global.add.v2.f32 [%0], {%1, %2};"
                 :: "l"(p), "f"(lo), "f"(hi) : "memory");
}
__device__ __forceinline__ void mma_bf16(float* c, const unsigned* a, unsigned b0, unsigned b1) {
    asm volatile(
        "mma.sync.aligned.m16n8k16.row.col.f32.bf16.bf16.f32 "
        "{%0,%1,%2,%3}, {%4,%5,%6,%7}, {%8,%9}, {%0,%1,%2,%3};"
        : "+f"(c[0]), "+f"(c[1]), "+f"(c[2]), "+f"(c[3])
        : "r"(a[0]), "r"(a[1]), "r"(a[2]), "r"(a[3]), "r"(b0), "r"(b1));
}
__device__ __forceinline__ unsigned split_pair(float v0, float v1, unsigned& lo_out) {
    __nv_bfloat162 hv = __floats2bfloat162_rn(v0, v1);
    float h0 = __bfloat162float(hv.x), h1 = __bfloat162float(hv.y);
    __nv_bfloat162 lv = __floats2bfloat162_rn(v0 - h0, v1 - h1);
    lo_out = *(unsigned*)&lv;
    return *(unsigned*)&hv;
}

// ---------------- K1: Q/K projection via mma.sync split-bf16, split-K ---------
// 1024 blocks (8b x 128 px-tiles of 128), 512 threads, 1 block/SM.
// Warps 0-7: ksteps 0-17; warps 8-15: ksteps 18-35 (same 8 warp-tile slots).
// High warps dump fp32 fragments to smem; low warps add + epilogue.
#define QKA_OFF 1024
#define QKB_OFF (1024 + 131072)
#define QK_SMEM (QKB_OFF + 65536)    /* 197632 B */

__device__ __forceinline__ void cvt_split8(const float* v, uint4& hi4, uint4& lo4) {
    unsigned hp[4], lp[4];
#pragma unroll
    for (int e = 0; e < 4; e++)
        hp[e] = split_pair(v[2 * e], v[2 * e + 1], lp[e]);
    hi4 = make_uint4(hp[0], hp[1], hp[2], hp[3]);
    lo4 = make_uint4(lp[0], lp[1], lp[2], lp[3]);
}

__global__ void __launch_bounds__(512, 1) k_qk(
    const float* __restrict__ x1,
    const float* __restrict__ Wq, const float* __restrict__ bq,
    const float* __restrict__ Wk, const float* __restrict__ bk)
{
    extern __shared__ __align__(16) char smem[];
    float* sbias = (float*)smem;
    int tid = threadIdx.x;
    int b  = blockIdx.x >> 7;
    int n0 = (blockIdx.x & 127) << 7;

    // zero accumulators for k_gmat
    {
        int z = blockIdx.x * 512 + tid;
        if (z < B_ * 33 * C_) g_G[z] = 0.0f;
        int zk = z - B_ * 33 * C_;
        if (zk >= 0 && zk < B_ * CQ) g_KS[zk] = 0.0f;
    }

    if (tid < 32)       sbias[tid] = bq[tid];
    else if (tid < 64)  sbias[tid] = bk[tid - 32];

    // stage A: x1 tile 128px x 192k -> hi at bytes [0,384), lo at [384,768)
    {
        int px = tid & 127, q4 = tid >> 7;   // 4 quarters x 6 chunks
        const float* xb = x1 + (size_t)b * C_ * N_ + n0 + px;
        char* arow = smem + QKA_OFF + px * 1024;
        unsigned sw = (px & 7) << 4;
        for (int c = q4 * 6; c < q4 * 6 + 6; c++) {
            float v[8];
#pragma unroll
            for (int j = 0; j < 8; j++) v[j] = xb[(size_t)(8 * c + j) * N_];
            uint4 hi4, lo4;
            cvt_split8(v, hi4, lo4);
            *(uint4*)(arow + ((16u * c) ^ sw))        = hi4;
            *(uint4*)(arow + ((384u + 16u * c) ^ sw)) = lo4;
        }
    }
    // stage B: W rows (0-31 Wq, 32-63 Wk) -> lo at [0,384), hi at [384,768)
    for (int i = tid; i < 1536; i += 512) {
        int n = i & 63, c = i >> 6;
        const float* wr = (n < 32) ? (Wq + (size_t)n * C_) : (Wk + (size_t)(n - 32) * C_);
        char* brow = smem + QKB_OFF + n * 1024;
        unsigned sw = (n & 7) << 4;
        float v[8];
#pragma unroll
        for (int j = 0; j < 8; j++) v[j] = wr[8 * c + j];
        uint4 hi4, lo4;
        cvt_split8(v, hi4, lo4);
        *(uint4*)(brow + ((16u * c) ^ sw))        = lo4;
        *(uint4*)(brow + ((384u + 16u * c) ^ sw)) = hi4;
    }
    __syncthreads();

    int lane = tid & 31, g = lane >> 2, t = lane & 3;
    int w = tid >> 5;
    int wk = w >> 3, slot = w & 7;
    int mpair = slot >> 1, nhalf = slot & 1;
    const char* Abase = smem + QKA_OFF + (mpair * 32) * 1024;
    const char* Bbase = smem + QKB_OFF + (nhalf * 32) * 1024;
    unsigned swg = (unsigned)g << 4;

    float cfr[2][4][4];
#pragma unroll
    for (int mt = 0; mt < 2; mt++)
#pragma unroll
        for (int nt = 0; nt < 4; nt++)
#pragma unroll
            for (int e = 0; e < 4; e++) cfr[mt][nt][e] = 0.f;

    int sbeg = wk * 18;
    for (int si = 0; si < 18; si++) {
        int s = sbeg + si;
        unsigned ka = (s < 24) ? 32u * s : 32u * (s - 24);
        unsigned kb = (s < 24) ? 32u * s : 384u + 32u * (s - 24);
        unsigned ka0 = (ka + 4 * t) ^ swg;
        unsigned ka1 = (ka + 4 * t + 16) ^ swg;
        unsigned kb0 = (kb + 4 * t) ^ swg;
        unsigned kb1 = (kb + 4 * t + 16) ^ swg;

        unsigned a[2][4];
#pragma unroll
        for (int mt = 0; mt < 2; mt++) {
            const char* r1 = Abase + (16 * mt + g) * 1024;
            const char* r2 = r1 + 8 * 1024;
            a[mt][0] = *(const unsigned*)(r1 + ka0);
            a[mt][1] = *(const unsigned*)(r2 + ka0);
            a[mt][2] = *(const unsigned*)(r1 + ka1);
            a[mt][3] = *(const unsigned*)(r2 + ka1);
        }
#pragma unroll
        for (int nt = 0; nt < 4; nt++) {
            const char* nr = Bbase + (nt * 8 + g) * 1024;
            unsigned b0 = *(const unsigned*)(nr + kb0);
            unsigned b1 = *(const unsigned*)(nr + kb1);
#pragma unroll
            for (int mt = 0; mt < 2; mt++)
                mma_bf16(cfr[mt][nt], a[mt], b0, b1);
        }
    }

    // combine split-K halves through smem (reuse A region; stride-33 rows)
    __syncthreads();
    float* dump = (float*)(smem + QKA_OFF);
    if (wk == 1) {
        float* dst = dump + slot * 1056 + lane * 33;
        int idx = 0;
#pragma unroll
        for (int mt = 0; mt < 2; mt++)
#pragma unroll
            for (int nt = 0; nt < 4; nt++)
#pragma unroll
                for (int e = 0; e < 4; e++) dst[idx++] = cfr[mt][nt][e];
    }
    __syncthreads();
    if (wk == 1) return;

    {
        const float* src = dump + slot * 1056 + lane * 33;
        int idx = 0;
#pragma unroll
        for (int mt = 0; mt < 2; mt++)
#pragma unroll
            for (int nt = 0; nt < 4; nt++)
#pragma unroll
                for (int e = 0; e < 4; e++) cfr[mt][nt][e] += src[idx++];
    }

    // epilogue: bias, L2 norm (reduce over t-group), store
#pragma unroll
    for (int mt = 0; mt < 2; mt++) {
        float s0 = 0.f, s1 = 0.f;
#pragma unroll
        for (int nt = 0; nt < 4; nt++) {
            float b0 = sbias[nhalf * 32 + nt * 8 + 2 * t];
            float b1 = sbias[nhalf * 32 + nt * 8 + 2 * t + 1];
            cfr[mt][nt][0] += b0; cfr[mt][nt][1] += b1;
            cfr[mt][nt][2] += b0; cfr[mt][nt][3] += b1;
            s0 += cfr[mt][nt][0] * cfr[mt][nt][0] + cfr[mt][nt][1] * cfr[mt][nt][1];
            s1 += cfr[mt][nt][2] * cfr[mt][nt][2] + cfr[mt][nt][3] * cfr[mt][nt][3];
        }
        s0 += __shfl_xor_sync(0xffffffffu, s0, 1);
        s0 += __shfl_xor_sync(0xffffffffu, s0, 2);
        s1 += __shfl_xor_sync(0xffffffffu, s1, 1);
        s1 += __shfl_xor_sync(0xffffffffu, s1, 2);
        float r0 = rsqrtf(s0), r1v = rsqrtf(s1);

        int px0 = n0 + mpair * 32 + 16 * mt + g;
        float* dst = nhalf ? g_Kn : g_Qn;
        float* d0 = dst + ((size_t)b * N_ + px0) * CQ;
        float* d1 = d0 + 8 * CQ;
#pragma unroll
        for (int nt = 0; nt < 4; nt++) {
            int col = nt * 8 + 2 * t;
            *(float2*)(d0 + col) = make_float2(cfr[mt][nt][0] * r0, cfr[mt][nt][1] * r0);
            *(float2*)(d1 + col) = make_float2(cfr[mt][nt][2] * r1v, cfr[mt][nt][3] * r1v);
        }
    }
}

// ---------------- K2: G = Kn^T @ x^T via mma.sync split-bf16 ------------------
#define GM_BH  0
#define GM_BL  27648
#define GM_AH  55296
#define GM_AL  59904
#define GM_SMEM 64512

__global__ void __launch_bounds__(256, 2) k_gmat(const float* __restrict__ x)
{
    extern __shared__ __align__(16) char smg[];
    char* Bh = smg + GM_BH;
    char* Bl = smg + GM_BL;
    char* Ah = smg + GM_AH;
    char* Al = smg + GM_AL;
    __shared__ float sKS[32];

    int tid = threadIdx.x, lane = tid & 31, w = tid >> 5;
    int g = lane >> 2, t = lane & 3;
    int mt = w & 1, ng = w >> 1;
    int b  = blockIdx.x >> 5;
    int n0 = (blockIdx.x & 31) << 9;

    const float* xb  = x + (size_t)b * C_ * N_ + n0;
    const float* knb = g_Kn + ((size_t)b * N_ + n0) * CQ;

    if (tid < 32) sKS[tid] = 0.f;

    float accf[6][4];
#pragma unroll
    for (int j = 0; j < 6; j++)
#pragma unroll
        for (int e = 0; e < 4; e++) accf[j][e] = 0.f;
    float xs[24];
#pragma unroll
    for (int j = 0; j < 24; j++) xs[j] = 0.f;
    float ksacc = 0.f;

    for (int s = 0; s < 8; s++) {
        int ns = s * 64;
        __syncthreads();

        // stage A: px 8w..8w+7, m = lane; k-pair-packed u32
        {
            float v[8];
#pragma unroll
            for (int j = 0; j < 8; j++) {
                v[j] = knb[(size_t)(ns + 8 * w + j) * CQ + lane];
                ksacc += v[j];
            }
#pragma unroll
            for (int jj = 0; jj < 4; jj++) {
                unsigned lo, hi = split_pair(v[2 * jj], v[2 * jj + 1], lo);
                *(unsigned*)(Ah + lane * 144 + (4 * w + jj) * 4) = hi;
                *(unsigned*)(Al + lane * 144 + (4 * w + jj) * 4) = lo;
            }
        }
        // stage B: rows w*24 .. w*24+23, 64 k (float2 per lane)
#pragma unroll
        for (int r0 = 0; r0 < 24; r0++) {
            int r = w * 24 + r0;
            float2 xv = *(const float2*)(xb + (size_t)r * N_ + ns + 2 * lane);
            xs[r0] += xv.x + xv.y;
            unsigned lo, hi = split_pair(xv.x, xv.y, lo);
            *(unsigned*)(Bh + r * 144 + 4 * lane) = hi;
            *(unsigned*)(Bl + r * 144 + 4 * lane) = lo;
        }
        __syncthreads();

        // MMA: 4 ksteps of 16
#pragma unroll
        for (int ks = 0; ks < 4; ks++) {
            unsigned ah[4], al[4];
            const char* ar0 = Ah + (16 * mt + g) * 144 + 32 * ks + 4 * t;
            const char* ar1 = ar0 + 8 * 144;
            ah[0] = *(const unsigned*)(ar0);
            ah[1] = *(const unsigned*)(ar1);
            ah[2] = *(const unsigned*)(ar0 + 16);
            ah[3] = *(const unsigned*)(ar1 + 16);
            const char* br0 = Al + (16 * mt + g) * 144 + 32 * ks + 4 * t;
            const char* br1 = br0 + 8 * 144;
            al[0] = *(const unsigned*)(br0);
            al[1] = *(const unsigned*)(br1);
            al[2] = *(const unsigned*)(br0 + 16);
            al[3] = *(const unsigned*)(br1 + 16);
#pragma unroll
            for (int j = 0; j < 6; j++) {
                int r = ng * 48 + j * 8 + g;
                const char* bhp = Bh + r * 144 + 32 * ks + 4 * t;
                const char* blp = Bl + r * 144 + 32 * ks + 4 * t;
                unsigned bh0 = *(const unsigned*)(bhp);
                unsigned bh1 = *(const unsigned*)(bhp + 16);
                unsigned bl0 = *(const unsigned*)(blp);
                unsigned bl1 = *(const unsigned*)(blp + 16);
                mma_bf16(accf[j], ah, bh0, bh1);   // hi*hi
                mma_bf16(accf[j], ah, bl0, bl1);   // hi*lo
                mma_bf16(accf[j], al, bh0, bh1);   // lo*hi
            }
        }
    }

    float* gb = g_G + b * 33 * C_;
#pragma unroll
    for (int j = 0; j < 6; j++) {
        int col = ng * 48 + j * 8 + 2 * t;
        red2(gb + (16 * mt + g) * C_ + col,     accf[j][0], accf[j][1]);
        red2(gb + (16 * mt + g + 8) * C_ + col, accf[j][2], accf[j][3]);
    }
#pragma unroll
    for (int j = 0; j < 24; j++) {
        float vv = xs[j];
        vv += __shfl_xor_sync(0xffffffffu, vv, 16);
        vv += __shfl_xor_sync(0xffffffffu, vv, 8);
        vv += __shfl_xor_sync(0xffffffffu, vv, 4);
        vv += __shfl_xor_sync(0xffffffffu, vv, 2);
        vv += __shfl_xor_sync(0xffffffffu, vv, 1);
        if (lane == 0) atomicAdd(gb + 32 * C_ + w * 24 + j, vv);
    }
    atomicAdd(&sKS[lane], ksacc);
    __syncthreads();
    if (tid < 32) atomicAdd(&g_KS[b * CQ + tid], sKS[tid]);
}

// ---------------- K3: M' = Ghat @ Wv^T + outer(coef, bv) ---------------------
__global__ void __launch_bounds__(128) k_small(
    const float* __restrict__ Wv, const float* __restrict__ bv)
{
    extern __shared__ float sms[];
    float* sG  = sms;                 // [33][192]
    float* sWv = sms + 33 * C_;       // [32][193]
    int tid = threadIdx.x;
    int b  = blockIdx.x / 6;
    int ct = blockIdx.x % 6;
    int cl = tid & 31, mg = tid >> 5;
    int c  = ct * 32 + cl;

    for (int i = tid; i < 33 * C_; i += 128) sG[i] = g_G[b * 33 * C_ + i];
    for (int i = tid; i < 32 * C_; i += 128) {
        int cc = i / C_, k = i % C_;
        sWv[cc * 193 + k] = Wv[(size_t)(ct * 32 + cc) * C_ + k];
    }
    __syncthreads();

    float bvc = bv[c];
    float a[9];
#pragma unroll
    for (int rr = 0; rr < 8; rr++) a[rr] = g_KS[b * CQ + mg * 8 + rr] * bvc;
    a[8] = (float)N_ * bvc;

    const float* wp = sWv + cl * 193;
    for (int k = 0; k < C_; k += 2) {
        float w0 = wp[k], w1 = wp[k + 1];
#pragma unroll
        for (int rr = 0; rr < 8; rr++) {
            int r = mg * 8 + rr;
            a[rr] = fmaf(w0, sG[r * C_ + k], a[rr]);
            a[rr] = fmaf(w1, sG[r * C_ + k + 1], a[rr]);
        }
        if (mg == 3) {
            a[8] = fmaf(w0, sG[32 * C_ + k], a[8]);
            a[8] = fmaf(w1, sG[32 * C_ + k + 1], a[8]);
        }
    }
#pragma unroll
    for (int rr = 0; rr < 8; rr++)
        g_M[(b * 33 + mg * 8 + rr) * C_ + c] = a[rr];
    if (mg == 3)
        g_M[(b * 33 + 32) * C_ + c] = a[8];
}

// ---------------- K4: out = A @ M' via mma.sync split-bf16 (direct stores) ----
#define KO_A_OFF  0
#define KO_B_OFF  26624                /* 128*208 */
#define KO_SMEM   (26624 + 19968)      /* + 96*208 = 46592 */

__global__ void __launch_bounds__(256, 3) k_out(
    const float* __restrict__ gamma, float* __restrict__ out)
{
    extern __shared__ __align__(16) char smo[];
    char* sA = smo + KO_A_OFF;
    char* sB = smo + KO_B_OFF;
    __shared__ float sKS[CQ];
    int tid = threadIdx.x;
    int b  = blockIdx.x >> 8;
    int ns = (blockIdx.x >> 1) & 127;
    int ch = blockIdx.x & 1;
    int n0 = ns << 7;

    if (tid < CQ) sKS[tid] = g_KS[b * CQ + tid] + EPSF;

    // stage B: 96 c-rows x 24 kk-pairs, hi+lo (transpose of g_M half)
    {
        const float* mb = g_M + b * 33 * C_ + ch * 96;
#pragma unroll
        for (int i = 0; i < 9; i++) {
            int j = tid + 256 * i;          // 2304 jobs
            int kk = j / 96, cc = j % 96;
            float m0 = (2 * kk < 33)     ? mb[(2 * kk) * C_ + cc]     : 0.f;
            float m1 = (2 * kk + 1 < 33) ? mb[(2 * kk + 1) * C_ + cc] : 0.f;
            unsigned lo, hi = split_pair(m0, m1, lo);
            *(unsigned*)(sB + cc * 208 + 4 * kk)      = hi;
            *(unsigned*)(sB + cc * 208 + 96 + 4 * kk) = lo;
        }
    }
    __syncthreads();          // sKS visible for A staging

    // stage A: row px = tid (tid<128): a[k] = g*Qn[k], a[32] = g
    if (tid < 128) {
        const float4* qsrc = (const float4*)(g_Qn + ((size_t)b * N_ + n0 + tid) * CQ);
        float qv[32];
#pragma unroll
        for (int jj = 0; jj < 8; jj++) {
            float4 v = qsrc[jj];
            qv[4 * jj] = v.x; qv[4 * jj + 1] = v.y;
            qv[4 * jj + 2] = v.z; qv[4 * jj + 3] = v.w;
        }
        float dot = 0.f;
#pragma unroll
        for (int m = 0; m < CQ; m++) dot += qv[m] * sKS[m];
        float gsc = gamma[0] / ((float)N_ + dot);

        char* arow = sA + tid * 208;
#pragma unroll
        for (int kk = 0; kk < 16; kk++) {
            unsigned lo, hi = split_pair(qv[2 * kk] * gsc, qv[2 * kk + 1] * gsc, lo);
            *(unsigned*)(arow + 4 * kk)      = hi;
            *(unsigned*)(arow + 96 + 4 * kk) = lo;
        }
        {   // kk = 16: (g, 0)
            unsigned lo, hi = split_pair(gsc, 0.f, lo);
            *(unsigned*)(arow + 64)      = hi;
            *(unsigned*)(arow + 96 + 64) = lo;
        }
#pragma unroll
        for (int kk = 17; kk < 24; kk++) {
            *(unsigned*)(arow + 4 * kk)      = 0u;
            *(unsigned*)(arow + 96 + 4 * kk) = 0u;
        }
    }
    __syncthreads();

    // MMA: warp w = m-tile (rows w*16 + g, +8), nt = 0..11, K=48
    int lane = tid & 31, g = lane >> 2, t = lane & 3;
    int w = tid >> 5;

    float cfr[12][4];
#pragma unroll
    for (int nt = 0; nt < 12; nt++)
#pragma unroll
        for (int e = 0; e < 4; e++) cfr[nt][e] = 0.f;

    const char* ar0 = sA + (w * 16 + g) * 208 + 4 * t;
    const char* ar1 = ar0 + 8 * 208;

#pragma unroll
    for (int ks = 0; ks < 3; ks++) {
        unsigned ah[4], al[4];
        ah[0] = *(const unsigned*)(ar0 + 32 * ks);
        ah[1] = *(const unsigned*)(ar1 + 32 * ks);
        ah[2] = *(const unsigned*)(ar0 + 32 * ks + 16);
        ah[3] = *(const unsigned*)(ar1 + 32 * ks + 16);
        al[0] = *(const unsigned*)(ar0 + 96 + 32 * ks);
        al[1] = *(const unsigned*)(ar1 + 96 + 32 * ks);
        al[2] = *(const unsigned*)(ar0 + 96 + 32 * ks + 16);
        al[3] = *(const unsigned*)(ar1 + 96 + 32 * ks + 16);
#pragma unroll
        for (int nt = 0; nt < 12; nt++) {
            const char* brow = sB + (nt * 8 + g) * 208 + 32 * ks + 4 * t;
            unsigned bh0 = *(const unsigned*)(brow);
            unsigned bh1 = *(const unsigned*)(brow + 16);
            mma_bf16(cfr[nt], ah, bh0, bh1);       // hi*hi
            mma_bf16(cfr[nt], al, bh0, bh1);       // lo*hi
            unsigned bl0 = *(const unsigned*)(brow + 96);
            unsigned bl1 = *(const unsigned*)(brow + 96 + 16);
            mma_bf16(cfr[nt], ah, bl0, bl1);       // hi*lo
        }
    }

    // epilogue: out[c][px]; rows g (c0,c1), g+8 (c2,c3)
    float* ob = out + ((size_t)b * C_ + ch * 96) * N_ + n0 + w * 16;
#pragma unroll
    for (int nt = 0; nt < 12; nt++) {
        int c = nt * 8 + 2 * t;
        ob[(size_t)c * N_ + g]           = cfr[nt][0];
        ob[(size_t)(c + 1) * N_ + g]     = cfr[nt][1];
        ob[(size_t)c * N_ + g + 8]       = cfr[nt][2];
        ob[(size_t)(c + 1) * N_ + g + 8] = cfr[nt][3];
    }
}

// ---------------- launch ------------------------------------------------------
extern "C" void kernel_launch(void* const* d_in, const int* in_sizes, int n_in,
                              void* d_out, int out_size)
{
    const float* x     = (const float*)d_in[0];
    const float* x1    = (const float*)d_in[1];
    const float* Wq    = (const float*)d_in[2];
    const float* bq    = (const float*)d_in[3];
    const float* Wk    = (const float*)d_in[4];
    const float* bk    = (const float*)d_in[5];
    const float* Wv    = (const float*)d_in[6];
    const float* bv    = (const float*)d_in[7];
    const float* gamma = (const float*)d_in[8];
    float* out = (float*)d_out;

    static int inited = 0;
    if (!inited) {
        cudaFuncSetAttribute(k_qk,    cudaFuncAttributeMaxDynamicSharedMemorySize, QK_SMEM);
        cudaFuncSetAttribute(k_gmat,  cudaFuncAttributeMaxDynamicSharedMemorySize, GM_SMEM);
        cudaFuncSetAttribute(k_small, cudaFuncAttributeMaxDynamicSharedMemorySize, 50080);
        cudaFuncSetAttribute(k_out,   cudaFuncAttributeMaxDynamicSharedMemorySize, KO_SMEM);
        inited = 1;
    }

    k_qk   <<<1024, 512, QK_SMEM>>>(x1, Wq, bq, Wk, bk);
    k_gmat <<<256, 256, GM_SMEM>>>(x);
    k_small<<<48, 128, 50080>>>(Wv, bv);
    k_out  <<<2048, 256, KO_SMEM>>>(gamma, out);
}